// round 13
// baseline (speedup 1.0000x reference)
#include <cuda_runtime.h>
#include <cuda_bf16.h>
#include <cuda_fp16.h>
#include <mma.h>
#include <math.h>
#include <cstdint>
#include <cstddef>

using namespace nvcuda;

#define BATCH 64
#define FRAMES 128
#define N_IN 512
#define N_HID 2048
#define ALPHA 0.5f
#define DECAY 0.5f
#define THR 0.5f

#define MEMS_ELEMS ((size_t)2 * BATCH * (FRAMES + 1) * N_HID)

// ---------------------------------------------------------------------------
// Device scratch
// ---------------------------------------------------------------------------
__device__ float g_U[2][BATCH * FRAMES][N_HID];  // x@W + bias
// A int8 4-limb pack: [layer][ntile(64)][chunk(16)][limb(4)][kin(128)][col(32)]
// chunk block = 16384B contiguous -> one TMA bulk per stage. (32MB)
__device__ __align__(256) signed char g_A8[(size_t)2 * 64 * 16 * 4 * 128 * 32];
// quantization scales per layer: T0..T3
__device__ float g_T[2][4];
__device__ float g_TInv[2][4];
__device__ int g_maxbits[2];
// x limbs (fp16 scaled)
__device__ __half g_X[3][(size_t)BATCH * FRAMES * N_IN];
// W limbs (fp16 scaled)
__device__ __half g_W[3][(size_t)2 * N_IN * N_HID];
// int8 spike scratch, ping-pong by parity
__device__ signed char g_s8[2][2][BATCH][N_HID];
// fp32 membrane scratch, ping-pong by parity
__device__ float g_mem[2][2][BATCH][N_HID];

// 3-limb scaled fp16 split (ff path, proven)
__device__ __forceinline__ void split3h(float a, __half& h0, __half& h1, __half& h2)
{
    float r = a;
    h0 = __float2half_rn(r);
    r -= __half2float(h0);
    h1 = __float2half_rn(r * 4096.0f);
    r -= __half2float(h1) * (1.0f / 4096.0f);
    h2 = __float2half_rn(r * 16777216.0f);
}

// ---------------------------------------------------------------------------
// A max-abs reduction + scale computation + int8 4-limb quantization
// ---------------------------------------------------------------------------
__global__ void zmax_kernel()
{
    g_maxbits[0] = 0;
    g_maxbits[1] = 0;
}

__global__ void maxA_kernel(const float* __restrict__ A1,
                            const float* __restrict__ A2)
{
    const int layer = blockIdx.y;
    const float* __restrict__ A = layer ? A2 : A1;
    size_t per = (size_t)N_HID * N_HID;
    float m = 0.f;
    for (size_t i = (size_t)blockIdx.x * blockDim.x + threadIdx.x; i < per;
         i += (size_t)gridDim.x * blockDim.x)
        m = fmaxf(m, fabsf(A[i]));
    // warp reduce
#pragma unroll
    for (int o = 16; o > 0; o >>= 1)
        m = fmaxf(m, __shfl_xor_sync(0xffffffffu, m, o));
    __shared__ float wm[32];
    int lane = threadIdx.x & 31, wid = threadIdx.x >> 5;
    if (lane == 0) wm[wid] = m;
    __syncthreads();
    if (wid == 0) {
        m = (lane < (int)(blockDim.x >> 5)) ? wm[lane] : 0.f;
#pragma unroll
        for (int o = 16; o > 0; o >>= 1)
            m = fmaxf(m, __shfl_xor_sync(0xffffffffu, m, o));
        if (lane == 0) atomicMax(&g_maxbits[layer], __float_as_int(m));
    }
}

__global__ void prepT_kernel()
{
    for (int l = 0; l < 2; l++) {
        float S = __int_as_float(g_maxbits[l]) * 1.0001f;
        if (!(S > 0.f)) S = 1.f;
        float T0 = S / 127.f;
        float T1 = T0 / 240.f;
        float T2 = T1 / 240.f;
        float T3 = T2 / 240.f;
        g_T[l][0] = T0; g_T[l][1] = T1; g_T[l][2] = T2; g_T[l][3] = T3;
        g_TInv[l][0] = 1.f / T0; g_TInv[l][1] = 1.f / T1;
        g_TInv[l][2] = 1.f / T2; g_TInv[l][3] = 1.f / T3;
    }
}

__global__ void prep_A8_kernel(const float* __restrict__ A1,
                               const float* __restrict__ A2)
{
    size_t per = (size_t)N_HID * N_HID;
    size_t idx = (size_t)blockIdx.x * blockDim.x + threadIdx.x;
    if (idx >= 2 * per) return;
    int layer = (int)(idx / per);
    size_t rem = idx % per;
    int k = (int)(rem / N_HID);
    int n = (int)(rem % N_HID);
    float a = (layer ? A2 : A1)[rem];

    int nt = n >> 5, col = n & 31;
    int chunk = k >> 7, kin = k & 127;
    size_t base = ((((size_t)(layer * 64 + nt) * 16 + chunk) * 4) * 128 + kin) * 32 + col;

    float r = a;
#pragma unroll
    for (int i = 0; i < 4; i++) {
        float T = g_T[layer][i];
        float q = rintf(r * g_TInv[layer][i]);
        q = fminf(fmaxf(q, -127.f), 127.f);
        r = fmaf(-q, T, r);
        g_A8[base + (size_t)i * (128 * 32)] = (signed char)(int)q;
    }
}

__global__ void prep_x3_kernel(const float* __restrict__ x)
{
    size_t total = (size_t)BATCH * FRAMES * N_IN;
    size_t idx = (size_t)blockIdx.x * blockDim.x + threadIdx.x;
    if (idx >= total) return;
    __half h0, h1, h2;
    split3h(x[idx], h0, h1, h2);
    g_X[0][idx] = h0; g_X[1][idx] = h1; g_X[2][idx] = h2;
}

__global__ void prep_W3_kernel(const float* __restrict__ W1,
                               const float* __restrict__ W2)
{
    size_t per = (size_t)N_IN * N_HID;
    size_t idx = (size_t)blockIdx.x * blockDim.x + threadIdx.x;
    if (idx >= 2 * per) return;
    float a = (idx < per) ? W1[idx] : W2[idx - per];
    __half h0, h1, h2;
    split3h(a, h0, h1, h2);
    g_W[0][idx] = h0; g_W[1][idx] = h1; g_W[2][idx] = h2;
}

// ---------------------------------------------------------------------------
// Feedforward GEMM via fp16 wmma, 6 limb-product passes (unchanged, proven)
// ---------------------------------------------------------------------------
__global__ void __launch_bounds__(256) ff_wmma_kernel(
    const float* __restrict__ b1, const float* __restrict__ b2)
{
    const int n0 = blockIdx.x * 64;
    const int m0 = blockIdx.y * 128;
    const int layer = blockIdx.z;

    __shared__ __half Xs[128][40];
    __shared__ __half Ws[32][72];

    const int tid = threadIdx.x;
    const int wid = tid >> 5;
    const int wm = wid >> 1;
    const int wn = (wid & 1) * 2;

    wmma::fragment<wmma::accumulator, 16, 16, 16, float> ctot[2][2];
#pragma unroll
    for (int i = 0; i < 2; i++)
#pragma unroll
        for (int j = 0; j < 2; j++) wmma::fill_fragment(ctot[i][j], 0.0f);

    const int PI[6] = {0, 0, 1, 0, 2, 1};
    const int PJ[6] = {0, 1, 0, 2, 0, 1};
    const float PS[6] = {1.0f, 0x1p-12f, 0x1p-12f, 0x1p-24f, 0x1p-24f, 0x1p-24f};

#pragma unroll 1
    for (int p = 0; p < 6; p++) {
        const __half* __restrict__ Xsrc = &g_X[PI[p]][0];
        const __half* __restrict__ Wsrc = &g_W[PJ[p]][(size_t)layer * N_IN * N_HID];

        wmma::fragment<wmma::accumulator, 16, 16, 16, float> acc[2][2];
#pragma unroll
        for (int i = 0; i < 2; i++)
#pragma unroll
            for (int j = 0; j < 2; j++) wmma::fill_fragment(acc[i][j], 0.0f);

#pragma unroll 1
        for (int k0 = 0; k0 < N_IN; k0 += 32) {
#pragma unroll
            for (int i = 0; i < 2; i++) {
                int idx = tid + i * 256;
                int row = idx >> 2;
                int q = (idx & 3) * 8;
                *(uint4*)&Xs[row][q] =
                    *(const uint4*)&Xsrc[(size_t)(m0 + row) * N_IN + k0 + q];
            }
            {
                int row = tid >> 3;
                int cc = (tid & 7) * 8;
                *(uint4*)&Ws[row][cc] =
                    *(const uint4*)&Wsrc[(size_t)(k0 + row) * N_HID + n0 + cc];
            }
            __syncthreads();

#pragma unroll
            for (int ks = 0; ks < 2; ks++) {
                wmma::fragment<wmma::matrix_a, 16, 16, 16, __half, wmma::row_major> af[2];
                wmma::fragment<wmma::matrix_b, 16, 16, 16, __half, wmma::row_major> bf[2];
#pragma unroll
                for (int i = 0; i < 2; i++)
                    wmma::load_matrix_sync(af[i], &Xs[(2 * wm + i) * 16][ks * 16], 40);
#pragma unroll
                for (int j = 0; j < 2; j++)
                    wmma::load_matrix_sync(bf[j], &Ws[ks * 16][(wn + j) * 16], 72);
#pragma unroll
                for (int i = 0; i < 2; i++)
#pragma unroll
                    for (int j = 0; j < 2; j++)
                        wmma::mma_sync(acc[i][j], af[i], bf[j], acc[i][j]);
            }
            __syncthreads();
        }

        const float sc = PS[p];
#pragma unroll
        for (int i = 0; i < 2; i++)
#pragma unroll
            for (int j = 0; j < 2; j++)
#pragma unroll
                for (int e = 0; e < ctot[0][0].num_elements; e++)
                    ctot[i][j].x[e] += acc[i][j].x[e] * sc;
    }

    const float* __restrict__ bias = layer ? b2 : b1;
    __shared__ float Cs[128][72];
#pragma unroll
    for (int i = 0; i < 2; i++)
#pragma unroll
        for (int j = 0; j < 2; j++)
            wmma::store_matrix_sync(&Cs[(2 * wm + i) * 16][(wn + j) * 16],
                                    ctot[i][j], 72, wmma::mem_row_major);
    __syncthreads();
    float* __restrict__ U = &g_U[layer][0][0];
#pragma unroll
    for (int e = 0; e < 32; e++) {
        int flat = tid + e * 256;
        int row = flat >> 6;
        int col = flat & 63;
        U[(size_t)(m0 + row) * N_HID + n0 + col] = Cs[row][col] + bias[n0 + col];
    }
}

// ---------------------------------------------------------------------------
// Init t=0 state (outputs + both scratches, parity 0)
// ---------------------------------------------------------------------------
__global__ void init_kernel(const float* __restrict__ mem0_1,
                            const float* __restrict__ mem0_2,
                            float* __restrict__ out)
{
    float* mems = out;
    float* spikes = out + MEMS_ELEMS;
    size_t idx = (size_t)blockIdx.x * blockDim.x + threadIdx.x;
    size_t total = (size_t)2 * BATCH * N_HID;
    if (idx >= total) return;
    int l = (int)(idx / ((size_t)BATCH * N_HID));
    size_t rem = idx % ((size_t)BATCH * N_HID);
    int b = (int)(rem / N_HID);
    int h = (int)(rem % N_HID);
    const float* m0 = l ? mem0_2 : mem0_1;
    float mv = m0[(size_t)b * N_HID + h];
    size_t o = ((size_t)(l * BATCH + b) * (FRAMES + 1)) * N_HID + h;
    __stwt(&mems[o], mv);
    __stwt(&spikes[o], 0.f);
    g_mem[0][l][b][h] = mv;
    g_s8[0][l][b][h] = 0;
}

// ---------------------------------------------------------------------------
// Fused pipelined step, int8 IMMA. Grid 128 = 2 layers x 64 coltiles(32).
// Block 1024 (32 warps): warp = (limb(4), m-tile(4), n-tile(2)).
// A via TMA bulk (16KB/chunk) + mbarrier, 4 stages; spikes int8 cp.async.
// ---------------------------------------------------------------------------
#define KC 128
#define NCH (N_HID / KC)                   // 16 chunks
#define NSTAGE 4
#define SS_STAGE_BYTES (64 * 144)          // 64 rows x 144 int8 (128 + 16 pad)
#define AS_STAGE_BYTES (4 * 128 * 32)      // 4 limbs x 128 k x 32 int8 = 16384
#define SS_OFF 0
#define AS_OFF (NSTAGE * SS_STAGE_BYTES)                  // 36864
#define CS_OFF (AS_OFF + NSTAGE * AS_STAGE_BYTES)         // 102400
#define CS_TILE_BYTES (64 * 36 * 4)                       // 9216 (int32)
#define MBAR_OFF (CS_OFF + 4 * CS_TILE_BYTES)             // 139264
#define STEP_SMEM_BYTES (MBAR_OFF + NSTAGE * 8 + 32)      // 139328

__device__ __forceinline__ void cpasync16(unsigned int dst, const void* src)
{
    asm volatile("cp.async.cg.shared.global [%0], [%1], 16;\n" ::"r"(dst), "l"(src));
}
__device__ __forceinline__ void mbar_init(unsigned int mbar, unsigned int count)
{
    asm volatile("mbarrier.init.shared.b64 [%0], %1;\n" ::"r"(mbar), "r"(count) : "memory");
}
__device__ __forceinline__ void mbar_expect_tx(unsigned int mbar, unsigned int bytes)
{
    asm volatile("mbarrier.arrive.expect_tx.shared.b64 _, [%0], %1;\n"
                 ::"r"(mbar), "r"(bytes) : "memory");
}
__device__ __forceinline__ void tma_bulk_1d(unsigned int dst, const void* src,
                                            unsigned int bytes, unsigned int mbar)
{
    asm volatile(
        "cp.async.bulk.shared::cta.global.mbarrier::complete_tx::bytes "
        "[%0], [%1], %2, [%3];\n"
        ::"r"(dst), "l"(src), "r"(bytes), "r"(mbar) : "memory");
}
__device__ __forceinline__ void mbar_wait(unsigned int mbar, unsigned int parity)
{
    unsigned int done;
    asm volatile(
        "{\n\t"
        ".reg .pred p;\n\t"
        "mbarrier.try_wait.parity.acquire.cta.shared::cta.b64 p, [%1], %2;\n\t"
        "selp.b32 %0, 1, 0, p;\n\t"
        "}"
        : "=r"(done) : "r"(mbar), "r"(parity) : "memory");
    if (!done) {
        asm volatile(
            "{\n\t"
            ".reg .pred P1;\n\t"
            "WAIT_LOOP_%=:\n\t"
            "mbarrier.try_wait.parity.acquire.cta.shared::cta.b64 P1, [%0], %1, 0x989680;\n\t"
            "@P1 bra.uni WAIT_DONE_%=;\n\t"
            "bra.uni WAIT_LOOP_%=;\n\t"
            "WAIT_DONE_%=:\n\t"
            "}"
            ::"r"(mbar), "r"(parity) : "memory");
    }
}

extern __shared__ char smem_buf[];

__global__ void __launch_bounds__(1024) step_mma_kernel(float* __restrict__ out, int t)
{
    const int bx = blockIdx.x;
    const int layer = bx >> 6;
    const int nt = bx & 63;
    const int n0 = nt * 32;

    const int tid = threadIdx.x;
    const int wid = tid >> 5;
    const int l   = wid >> 3;      // limb 0..3
    const int w8  = wid & 7;
    const int wm  = w8 >> 1;       // 0..3 m-tile
    const int wn  = w8 & 1;        // 0..1 n-tile

    float* mems = out;
    float* spikes = out + MEMS_ELEMS;

    const signed char* __restrict__ Abase =
        g_A8 + (size_t)(layer * 64 + nt) * (16 * AS_STAGE_BYTES);
    const signed char* __restrict__ gS = &g_s8[t & 1][layer][0][0];
    const float* __restrict__ gM = &g_mem[t & 1][layer][0][0];

    const unsigned int smem_u32 = (unsigned int)__cvta_generic_to_shared(smem_buf);
    const unsigned int mbar0 = smem_u32 + MBAR_OFF;

    if (tid == 0) {
#pragma unroll
        for (int s = 0; s < NSTAGE; s++) mbar_init(mbar0 + s * 8, 1);
    }
    __syncthreads();

    wmma::fragment<wmma::accumulator, 16, 16, 16, int> acc;
    wmma::fill_fragment(acc, 0);

    // spike copy map: first 512 threads stage 64 rows x 128B
    const int sb = (tid & 511) >> 3;
    const int scb = tid & 7;

    auto issue_stage = [&](int c, int s) {
        if (tid == 0) {
            unsigned int mb = mbar0 + s * 8;
            mbar_expect_tx(mb, AS_STAGE_BYTES);
            tma_bulk_1d(smem_u32 + AS_OFF + s * AS_STAGE_BYTES,
                        (const char*)Abase + (size_t)c * AS_STAGE_BYTES,
                        AS_STAGE_BYTES, mb);
        }
        if (tid < 512) {
            const char* srcS = (const char*)(gS + (size_t)sb * N_HID + c * KC);
            unsigned int dstS = smem_u32 + SS_OFF + s * SS_STAGE_BYTES + sb * 144;
            cpasync16(dstS + scb * 16, srcS + scb * 16);
        }
        asm volatile("cp.async.commit_group;\n" ::: "memory");
    };

    issue_stage(0, 0);
    issue_stage(1, 1);
    issue_stage(2, 2);

#pragma unroll 1
    for (int c = 0; c < NCH; c++) {
        const int rem = NCH - 1 - c;
        if (rem >= 2)
            asm volatile("cp.async.wait_group 2;\n" ::: "memory");
        else if (rem == 1)
            asm volatile("cp.async.wait_group 1;\n" ::: "memory");
        else
            asm volatile("cp.async.wait_group 0;\n" ::: "memory");
        const int s = c & (NSTAGE - 1);
        mbar_wait(mbar0 + s * 8, (c >> 2) & 1);
        __syncthreads();

        if (c + 3 < NCH) issue_stage(c + 3, (c + 3) & (NSTAGE - 1));

        const signed char* ssb =
            (const signed char*)(smem_buf + SS_OFF + s * SS_STAGE_BYTES);
        const signed char* asb =
            (const signed char*)(smem_buf + AS_OFF + s * AS_STAGE_BYTES);

#pragma unroll
        for (int ks = 0; ks < KC / 16; ks++) {
            wmma::fragment<wmma::matrix_a, 16, 16, 16, signed char, wmma::row_major> af;
            wmma::load_matrix_sync(af, ssb + (wm * 16) * 144 + ks * 16, 144);
            wmma::fragment<wmma::matrix_b, 16, 16, 16, signed char, wmma::row_major> bfr;
            wmma::load_matrix_sync(bfr, asb + (l * 128 + ks * 16) * 32 + wn * 16, 32);
            wmma::mma_sync(acc, af, bfr, acc);
        }
    }

    // store per-limb integer partials
    int* Cl = (int*)(smem_buf + CS_OFF + l * CS_TILE_BYTES);
    __syncthreads();
    wmma::store_matrix_sync(Cl + (wm * 16) * 36 + wn * 16, acc, 36,
                            wmma::mem_row_major);
    __syncthreads();

    // fused LIF epilogue: p = c0*T0 + c1*T1 + c2*T2 + c3*T3 (nested fma, small->large)
    const int* Cs0 = (const int*)(smem_buf + CS_OFF);
    const int* Cs1 = (const int*)(smem_buf + CS_OFF + CS_TILE_BYTES);
    const int* Cs2 = (const int*)(smem_buf + CS_OFF + 2 * CS_TILE_BYTES);
    const int* Cs3 = (const int*)(smem_buf + CS_OFF + 3 * CS_TILE_BYTES);
    const float T0 = g_T[layer][0], T1 = g_T[layer][1];
    const float T2 = g_T[layer][2], T3 = g_T[layer][3];
    signed char* gSn = &g_s8[(t + 1) & 1][layer][0][0];
    float* gMn = &g_mem[(t + 1) & 1][layer][0][0];
#pragma unroll
    for (int e = 0; e < 2; e++) {
        int flat = tid + e * 1024;   // 0..2047
        int b = flat >> 5;
        int hl = flat & 31;
        int h = n0 + hl;
        int o = b * 36 + hl;
        float p = fmaf((float)Cs0[o], T0,
                  fmaf((float)Cs1[o], T1,
                  fmaf((float)Cs2[o], T2, (float)Cs3[o] * T3)));
        float u = __ldcs(&g_U[layer][b * FRAMES + t][h]);
        size_t row_t1 =
            ((size_t)(layer * BATCH + b) * (FRAMES + 1) + t + 1) * N_HID + h;
        float mprev = gM[(size_t)b * N_HID + h];
        float sprev = (float)gS[(size_t)b * N_HID + h];
        float y = tanhf(ALPHA * p + (1.0f - ALPHA) * u);
        float mn = DECAY * mprev - THR * (1.0f - sprev) + y;
        float sn = (mn > THR) ? 1.0f : 0.0f;
        __stwt(&mems[row_t1], mn);
        __stwt(&spikes[row_t1], sn);
        gMn[(size_t)b * N_HID + h] = mn;
        gSn[(size_t)b * N_HID + h] = (signed char)(mn > THR);
    }
}

// ---------------------------------------------------------------------------
// Launch. Inputs: x, W_in1, A1, b1, W_in2, A2, b2, mem0_1, mem0_2
// ---------------------------------------------------------------------------
extern "C" void kernel_launch(void* const* d_in, const int* in_sizes, int n_in,
                              void* d_out, int out_size)
{
    const float* x      = (const float*)d_in[0];
    const float* W_in1  = (const float*)d_in[1];
    const float* A1     = (const float*)d_in[2];
    const float* b1     = (const float*)d_in[3];
    const float* W_in2  = (const float*)d_in[4];
    const float* A2     = (const float*)d_in[5];
    const float* b2     = (const float*)d_in[6];
    const float* mem0_1 = (const float*)d_in[7];
    const float* mem0_2 = (const float*)d_in[8];
    float* out = (float*)d_out;

    cudaFuncSetAttribute(step_mma_kernel,
                         cudaFuncAttributeMaxDynamicSharedMemorySize,
                         STEP_SMEM_BYTES);

    // A quantization: max -> scales -> int8 4-limb pack
    zmax_kernel<<<1, 1>>>();
    {
        dim3 grid(512, 2);
        maxA_kernel<<<grid, 256>>>(A1, A2);
    }
    prepT_kernel<<<1, 1>>>();
    {
        size_t n = (size_t)2 * N_HID * N_HID;
        prep_A8_kernel<<<(unsigned)((n + 255) / 256), 256>>>(A1, A2);
    }
    // ff limb packs
    {
        size_t n = (size_t)BATCH * FRAMES * N_IN;
        prep_x3_kernel<<<(unsigned)((n + 255) / 256), 256>>>(x);
    }
    {
        size_t n = (size_t)2 * N_IN * N_HID;
        prep_W3_kernel<<<(unsigned)((n + 255) / 256), 256>>>(W_in1, W_in2);
    }

    // Feedforward drive on tensor cores (includes bias)
    {
        dim3 grid(N_HID / 64, (BATCH * FRAMES) / 128, 2);
        ff_wmma_kernel<<<grid, 256>>>(b1, b2);
    }

    // t=0 state
    {
        int total = 2 * BATCH * N_HID;
        init_kernel<<<(total + 255) / 256, 256>>>(mem0_1, mem0_2, out);
    }

    // Sequential time loop
    for (int t = 0; t < FRAMES; t++) {
        step_mma_kernel<<<128, 1024, STEP_SMEM_BYTES>>>(out, t);
    }
}

// round 14
// speedup vs baseline: 1.7727x; 1.7727x over previous
#include <cuda_runtime.h>
#include <cuda_bf16.h>
#include <cuda_fp16.h>
#include <mma.h>
#include <math.h>
#include <cstdint>
#include <cstddef>

using namespace nvcuda;

#define BATCH 64
#define FRAMES 128
#define N_IN 512
#define N_HID 2048
#define ALPHA 0.5f
#define DECAY 0.5f
#define THR 0.5f

#define MEMS_ELEMS ((size_t)2 * BATCH * (FRAMES + 1) * N_HID)

// ---------------------------------------------------------------------------
// Device scratch
// ---------------------------------------------------------------------------
__device__ float g_U[2][BATCH * FRAMES][N_HID];  // x@W + bias
// A limbs (fp16, scaled 1 / 2^12 / 2^24), UNPADDED 64B rows:
// [layer][ntile(64)][chunk(16)][limb(3)][kin(128)][col(32)] -> one chunk
// = 384 rows x 64B = 24576B contiguous => single TMA bulk per stage. (48MB)
__device__ __align__(256) __half g_Apack[(size_t)2 * 64 * 16 * 3 * 128 * 32];
// x limbs (fp16 scaled)
__device__ __half g_X[3][(size_t)BATCH * FRAMES * N_IN];
// W limbs (fp16 scaled)
__device__ __half g_W[3][(size_t)2 * N_IN * N_HID];
// fp16 spike scratch, ping-pong by parity
__device__ __half g_sbf[2][2][BATCH][N_HID];
// fp32 membrane scratch, ping-pong by parity
__device__ float g_mem[2][2][BATCH][N_HID];

// 3-limb scaled fp16 split: a = h0 + h1*2^-12 + h2*2^-24 + r, |r| ~ 2^-36|a|
__device__ __forceinline__ void split3h(float a, __half& h0, __half& h1, __half& h2)
{
    float r = a;
    h0 = __float2half_rn(r);
    r -= __half2float(h0);
    h1 = __float2half_rn(r * 4096.0f);
    r -= __half2float(h1) * (1.0f / 4096.0f);
    h2 = __float2half_rn(r * 16777216.0f);
}

__global__ void prep_A3_kernel(const float* __restrict__ A1,
                               const float* __restrict__ A2)
{
    size_t per = (size_t)N_HID * N_HID;
    size_t idx = (size_t)blockIdx.x * blockDim.x + threadIdx.x;
    if (idx >= 2 * per) return;
    int layer = (int)(idx / per);
    size_t rem = idx % per;
    int k = (int)(rem / N_HID);
    int n = (int)(rem % N_HID);
    float a = (layer ? A2 : A1)[rem];

    int nt = n >> 5, col = n & 31;
    int chunk = k >> 7, kin = k & 127;
    size_t row0 = (((size_t)(layer * 64 + nt) * 16 + chunk) * 3) * 128 + kin;

    __half h0, h1, h2;
    split3h(a, h0, h1, h2);
    g_Apack[(row0 + 0 * 128) * 32 + col] = h0;
    g_Apack[(row0 + 1 * 128) * 32 + col] = h1;
    g_Apack[(row0 + 2 * 128) * 32 + col] = h2;
}

__global__ void prep_x3_kernel(const float* __restrict__ x)
{
    size_t total = (size_t)BATCH * FRAMES * N_IN;
    size_t idx = (size_t)blockIdx.x * blockDim.x + threadIdx.x;
    if (idx >= total) return;
    __half h0, h1, h2;
    split3h(x[idx], h0, h1, h2);
    g_X[0][idx] = h0; g_X[1][idx] = h1; g_X[2][idx] = h2;
}

__global__ void prep_W3_kernel(const float* __restrict__ W1,
                               const float* __restrict__ W2)
{
    size_t per = (size_t)N_IN * N_HID;
    size_t idx = (size_t)blockIdx.x * blockDim.x + threadIdx.x;
    if (idx >= 2 * per) return;
    float a = (idx < per) ? W1[idx] : W2[idx - per];
    __half h0, h1, h2;
    split3h(a, h0, h1, h2);
    g_W[0][idx] = h0; g_W[1][idx] = h1; g_W[2][idx] = h2;
}

// ---------------------------------------------------------------------------
// Feedforward GEMM via fp16 wmma, 6 limb-product passes (unchanged, proven)
// ---------------------------------------------------------------------------
__global__ void __launch_bounds__(256) ff_wmma_kernel(
    const float* __restrict__ b1, const float* __restrict__ b2)
{
    const int n0 = blockIdx.x * 64;
    const int m0 = blockIdx.y * 128;
    const int layer = blockIdx.z;

    __shared__ __half Xs[128][40];
    __shared__ __half Ws[32][72];

    const int tid = threadIdx.x;
    const int wid = tid >> 5;
    const int wm = wid >> 1;
    const int wn = (wid & 1) * 2;

    wmma::fragment<wmma::accumulator, 16, 16, 16, float> ctot[2][2];
#pragma unroll
    for (int i = 0; i < 2; i++)
#pragma unroll
        for (int j = 0; j < 2; j++) wmma::fill_fragment(ctot[i][j], 0.0f);

    const int PI[6] = {0, 0, 1, 0, 2, 1};
    const int PJ[6] = {0, 1, 0, 2, 0, 1};
    const float PS[6] = {1.0f, 0x1p-12f, 0x1p-12f, 0x1p-24f, 0x1p-24f, 0x1p-24f};

#pragma unroll 1
    for (int p = 0; p < 6; p++) {
        const __half* __restrict__ Xsrc = &g_X[PI[p]][0];
        const __half* __restrict__ Wsrc = &g_W[PJ[p]][(size_t)layer * N_IN * N_HID];

        wmma::fragment<wmma::accumulator, 16, 16, 16, float> acc[2][2];
#pragma unroll
        for (int i = 0; i < 2; i++)
#pragma unroll
            for (int j = 0; j < 2; j++) wmma::fill_fragment(acc[i][j], 0.0f);

#pragma unroll 1
        for (int k0 = 0; k0 < N_IN; k0 += 32) {
#pragma unroll
            for (int i = 0; i < 2; i++) {
                int idx = tid + i * 256;
                int row = idx >> 2;
                int q = (idx & 3) * 8;
                *(uint4*)&Xs[row][q] =
                    *(const uint4*)&Xsrc[(size_t)(m0 + row) * N_IN + k0 + q];
            }
            {
                int row = tid >> 3;
                int cc = (tid & 7) * 8;
                *(uint4*)&Ws[row][cc] =
                    *(const uint4*)&Wsrc[(size_t)(k0 + row) * N_HID + n0 + cc];
            }
            __syncthreads();

#pragma unroll
            for (int ks = 0; ks < 2; ks++) {
                wmma::fragment<wmma::matrix_a, 16, 16, 16, __half, wmma::row_major> af[2];
                wmma::fragment<wmma::matrix_b, 16, 16, 16, __half, wmma::row_major> bf[2];
#pragma unroll
                for (int i = 0; i < 2; i++)
                    wmma::load_matrix_sync(af[i], &Xs[(2 * wm + i) * 16][ks * 16], 40);
#pragma unroll
                for (int j = 0; j < 2; j++)
                    wmma::load_matrix_sync(bf[j], &Ws[ks * 16][(wn + j) * 16], 72);
#pragma unroll
                for (int i = 0; i < 2; i++)
#pragma unroll
                    for (int j = 0; j < 2; j++)
                        wmma::mma_sync(acc[i][j], af[i], bf[j], acc[i][j]);
            }
            __syncthreads();
        }

        const float sc = PS[p];
#pragma unroll
        for (int i = 0; i < 2; i++)
#pragma unroll
            for (int j = 0; j < 2; j++)
#pragma unroll
                for (int e = 0; e < ctot[0][0].num_elements; e++)
                    ctot[i][j].x[e] += acc[i][j].x[e] * sc;
    }

    const float* __restrict__ bias = layer ? b2 : b1;
    __shared__ float Cs[128][72];
#pragma unroll
    for (int i = 0; i < 2; i++)
#pragma unroll
        for (int j = 0; j < 2; j++)
            wmma::store_matrix_sync(&Cs[(2 * wm + i) * 16][(wn + j) * 16],
                                    ctot[i][j], 72, wmma::mem_row_major);
    __syncthreads();
    float* __restrict__ U = &g_U[layer][0][0];
#pragma unroll
    for (int e = 0; e < 32; e++) {
        int flat = tid + e * 256;
        int row = flat >> 6;
        int col = flat & 63;
        U[(size_t)(m0 + row) * N_HID + n0 + col] = Cs[row][col] + bias[n0 + col];
    }
}

// ---------------------------------------------------------------------------
// Init t=0 state (outputs + both scratches, parity 0)
// ---------------------------------------------------------------------------
__global__ void init_kernel(const float* __restrict__ mem0_1,
                            const float* __restrict__ mem0_2,
                            float* __restrict__ out)
{
    float* mems = out;
    float* spikes = out + MEMS_ELEMS;
    size_t idx = (size_t)blockIdx.x * blockDim.x + threadIdx.x;
    size_t total = (size_t)2 * BATCH * N_HID;
    if (idx >= total) return;
    int l = (int)(idx / ((size_t)BATCH * N_HID));
    size_t rem = idx % ((size_t)BATCH * N_HID);
    int b = (int)(rem / N_HID);
    int h = (int)(rem % N_HID);
    const float* m0 = l ? mem0_2 : mem0_1;
    float mv = m0[(size_t)b * N_HID + h];
    size_t o = ((size_t)(l * BATCH + b) * (FRAMES + 1)) * N_HID + h;
    __stwt(&mems[o], mv);
    __stwt(&spikes[o], 0.f);
    g_mem[0][l][b][h] = mv;
    g_sbf[0][l][b][h] = __float2half(0.f);
}

// ---------------------------------------------------------------------------
// Fused pipelined step (R12 base, unpadded A). Grid 128. Block 768 (24 warps):
// warp = (limb(3), m-tile(4), n-tile(2)). A via TMA bulk + mbarrier, 4 stages.
// ---------------------------------------------------------------------------
#define KC 128
#define NCH (N_HID / KC)                   // 16 chunks
#define NSTAGE 4
#define SS_STAGE_BYTES (64 * 272)          // 64 rows x 136 fp16
#define AS_STAGE_BYTES (384 * 64)          // 3 limbs x 128 k x 32 fp16 = 24576
#define SS_OFF 0
#define AS_OFF (NSTAGE * SS_STAGE_BYTES)                  // 69632
#define CS_OFF (AS_OFF + NSTAGE * AS_STAGE_BYTES)         // 167936
#define CS_TILE_BYTES (64 * 36 * 4)                       // 9216
#define MBAR_OFF (CS_OFF + 3 * CS_TILE_BYTES)             // 195584
#define STEP_SMEM_BYTES (MBAR_OFF + NSTAGE * 8 + 32)      // 195648

__device__ __forceinline__ void cpasync16(unsigned int dst, const void* src)
{
    asm volatile("cp.async.cg.shared.global [%0], [%1], 16;\n" ::"r"(dst), "l"(src));
}
__device__ __forceinline__ void mbar_init(unsigned int mbar, unsigned int count)
{
    asm volatile("mbarrier.init.shared.b64 [%0], %1;\n" ::"r"(mbar), "r"(count) : "memory");
}
__device__ __forceinline__ void mbar_expect_tx(unsigned int mbar, unsigned int bytes)
{
    asm volatile("mbarrier.arrive.expect_tx.shared.b64 _, [%0], %1;\n"
                 ::"r"(mbar), "r"(bytes) : "memory");
}
__device__ __forceinline__ void tma_bulk_1d(unsigned int dst, const void* src,
                                            unsigned int bytes, unsigned int mbar)
{
    asm volatile(
        "cp.async.bulk.shared::cta.global.mbarrier::complete_tx::bytes "
        "[%0], [%1], %2, [%3];\n"
        ::"r"(dst), "l"(src), "r"(bytes), "r"(mbar) : "memory");
}
__device__ __forceinline__ void mbar_wait(unsigned int mbar, unsigned int parity)
{
    unsigned int done;
    asm volatile(
        "{\n\t"
        ".reg .pred p;\n\t"
        "mbarrier.try_wait.parity.acquire.cta.shared::cta.b64 p, [%1], %2;\n\t"
        "selp.b32 %0, 1, 0, p;\n\t"
        "}"
        : "=r"(done) : "r"(mbar), "r"(parity) : "memory");
    if (!done) {
        asm volatile(
            "{\n\t"
            ".reg .pred P1;\n\t"
            "WAIT_LOOP_%=:\n\t"
            "mbarrier.try_wait.parity.acquire.cta.shared::cta.b64 P1, [%0], %1, 0x989680;\n\t"
            "@P1 bra.uni WAIT_DONE_%=;\n\t"
            "bra.uni WAIT_LOOP_%=;\n\t"
            "WAIT_DONE_%=:\n\t"
            "}"
            ::"r"(mbar), "r"(parity) : "memory");
    }
}

extern __shared__ char smem_buf[];

__global__ void __launch_bounds__(768) step_mma_kernel(float* __restrict__ out, int t)
{
    const int bx = blockIdx.x;
    const int layer = bx >> 6;
    const int nt = bx & 63;
    const int n0 = nt * 32;

    const int tid = threadIdx.x;
    const int wid = tid >> 5;
    const int l   = wid >> 3;      // limb 0..2
    const int w8  = wid & 7;
    const int wm  = w8 >> 1;       // 0..3 m-tile
    const int wn  = w8 & 1;        // 0..1 n-tile

    float* mems = out;
    float* spikes = out + MEMS_ELEMS;

    const __half* __restrict__ Abase =
        g_Apack + (size_t)(layer * 64 + nt) * (16 * 3 * 128 * 32);
    const __half* __restrict__ gS = &g_sbf[t & 1][layer][0][0];
    const float* __restrict__ gM = &g_mem[t & 1][layer][0][0];

    const unsigned int smem_u32 = (unsigned int)__cvta_generic_to_shared(smem_buf);
    const unsigned int mbar0 = smem_u32 + MBAR_OFF;

    if (tid == 0) {
#pragma unroll
        for (int s = 0; s < NSTAGE; s++) mbar_init(mbar0 + s * 8, 1);
    }
    __syncthreads();

    wmma::fragment<wmma::accumulator, 16, 16, 16, float> acc;
    wmma::fill_fragment(acc, 0.0f);

    // spike copy map: first 512 threads
    const int sb = (tid & 511) >> 3;
    const int scb = tid & 7;

    auto issue_stage = [&](int c, int s) {
        if (tid == 0) {
            unsigned int mb = mbar0 + s * 8;
            mbar_expect_tx(mb, AS_STAGE_BYTES);
            tma_bulk_1d(smem_u32 + AS_OFF + s * AS_STAGE_BYTES,
                        (const char*)Abase + (size_t)c * AS_STAGE_BYTES,
                        AS_STAGE_BYTES, mb);
        }
        if (tid < 512) {
            const char* srcS = (const char*)(gS + (size_t)sb * N_HID + c * KC);
            unsigned int dstS = smem_u32 + SS_OFF + s * SS_STAGE_BYTES + sb * 272;
#pragma unroll
            for (int i = 0; i < 2; i++) {
                int cc = scb + i * 8;
                cpasync16(dstS + cc * 16, srcS + cc * 16);
            }
        }
        asm volatile("cp.async.commit_group;\n" ::: "memory");
    };

    issue_stage(0, 0);
    issue_stage(1, 1);
    issue_stage(2, 2);

#pragma unroll 1
    for (int c = 0; c < NCH; c++) {
        const int rem = NCH - 1 - c;
        if (rem >= 2)
            asm volatile("cp.async.wait_group 2;\n" ::: "memory");
        else if (rem == 1)
            asm volatile("cp.async.wait_group 1;\n" ::: "memory");
        else
            asm volatile("cp.async.wait_group 0;\n" ::: "memory");
        const int s = c & (NSTAGE - 1);
        mbar_wait(mbar0 + s * 8, (c >> 2) & 1);
        __syncthreads();

        if (c + 3 < NCH) issue_stage(c + 3, (c + 3) & (NSTAGE - 1));

        const __half* ssb = (const __half*)(smem_buf + SS_OFF + s * SS_STAGE_BYTES);
        const __half* asb = (const __half*)(smem_buf + AS_OFF + s * AS_STAGE_BYTES);

#pragma unroll
        for (int ks = 0; ks < KC / 16; ks++) {
            wmma::fragment<wmma::matrix_a, 16, 16, 16, __half, wmma::row_major> af;
            wmma::load_matrix_sync(af, ssb + (wm * 16) * 136 + ks * 16, 136);
            wmma::fragment<wmma::matrix_b, 16, 16, 16, __half, wmma::row_major> bfr;
            wmma::load_matrix_sync(bfr, asb + (l * 128 + ks * 16) * 32 + wn * 16, 32);
            wmma::mma_sync(acc, af, bfr, acc);
        }
    }

    // store raw per-limb partials; scaling happens in the epilogue
    float* Cl = (float*)(smem_buf + CS_OFF + l * CS_TILE_BYTES);
    __syncthreads();
    wmma::store_matrix_sync(Cl + (wm * 16) * 36 + wn * 16, acc, 36,
                            wmma::mem_row_major);
    __syncthreads();

    // fused LIF epilogue: p = fma(c1, 2^-12, c0) + c2*2^-24
    const float* Cs0 = (const float*)(smem_buf + CS_OFF);
    const float* Cs1 = (const float*)(smem_buf + CS_OFF + CS_TILE_BYTES);
    const float* Cs2 = (const float*)(smem_buf + CS_OFF + 2 * CS_TILE_BYTES);
    __half* gSn = &g_sbf[(t + 1) & 1][layer][0][0];
    float* gMn = &g_mem[(t + 1) & 1][layer][0][0];
#pragma unroll
    for (int e = 0; e < 3; e++) {
        int flat = tid + e * 768;   // 0..2303, guard to 2048
        if (flat < 2048) {
            int b = flat >> 5;
            int hl = flat & 31;
            int h = n0 + hl;
            float p = fmaf(Cs1[b * 36 + hl], 0x1p-12f, Cs0[b * 36 + hl])
                      + Cs2[b * 36 + hl] * 0x1p-24f;
            float u = __ldcs(&g_U[layer][b * FRAMES + t][h]);
            size_t row_t1 =
                ((size_t)(layer * BATCH + b) * (FRAMES + 1) + t + 1) * N_HID + h;
            float mprev = gM[(size_t)b * N_HID + h];
            float sprev = __half2float(gS[(size_t)b * N_HID + h]);
            float y = tanhf(ALPHA * p + (1.0f - ALPHA) * u);
            float mn = DECAY * mprev - THR * (1.0f - sprev) + y;
            float sn = (mn > THR) ? 1.0f : 0.0f;
            __stwt(&mems[row_t1], mn);
            __stwt(&spikes[row_t1], sn);
            gMn[(size_t)b * N_HID + h] = mn;
            gSn[(size_t)b * N_HID + h] = __float2half(sn);
        }
    }
}

// ---------------------------------------------------------------------------
// Launch. Inputs: x, W_in1, A1, b1, W_in2, A2, b2, mem0_1, mem0_2
// ---------------------------------------------------------------------------
extern "C" void kernel_launch(void* const* d_in, const int* in_sizes, int n_in,
                              void* d_out, int out_size)
{
    const float* x      = (const float*)d_in[0];
    const float* W_in1  = (const float*)d_in[1];
    const float* A1     = (const float*)d_in[2];
    const float* b1     = (const float*)d_in[3];
    const float* W_in2  = (const float*)d_in[4];
    const float* A2     = (const float*)d_in[5];
    const float* b2     = (const float*)d_in[6];
    const float* mem0_1 = (const float*)d_in[7];
    const float* mem0_2 = (const float*)d_in[8];
    float* out = (float*)d_out;

    cudaFuncSetAttribute(step_mma_kernel,
                         cudaFuncAttributeMaxDynamicSharedMemorySize,
                         STEP_SMEM_BYTES);

    // limb packs
    {
        size_t n = (size_t)2 * N_HID * N_HID;
        prep_A3_kernel<<<(unsigned)((n + 255) / 256), 256>>>(A1, A2);
    }
    {
        size_t n = (size_t)BATCH * FRAMES * N_IN;
        prep_x3_kernel<<<(unsigned)((n + 255) / 256), 256>>>(x);
    }
    {
        size_t n = (size_t)2 * N_IN * N_HID;
        prep_W3_kernel<<<(unsigned)((n + 255) / 256), 256>>>(W_in1, W_in2);
    }

    // Feedforward drive on tensor cores (includes bias)
    {
        dim3 grid(N_HID / 64, (BATCH * FRAMES) / 128, 2);
        ff_wmma_kernel<<<grid, 256>>>(b1, b2);
    }

    // t=0 state
    {
        int total = 2 * BATCH * N_HID;
        init_kernel<<<(total + 255) / 256, 256>>>(mem0_1, mem0_2, out);
    }

    // Sequential time loop
    for (int t = 0; t < FRAMES; t++) {
        step_mma_kernel<<<128, 768, STEP_SMEM_BYTES>>>(out, t);
    }
}

// round 15
// speedup vs baseline: 2.8932x; 1.6320x over previous
#include <cuda_runtime.h>
#include <cuda_bf16.h>
#include <cuda_fp16.h>
#include <mma.h>
#include <math.h>
#include <cstdint>
#include <cstddef>

using namespace nvcuda;

#define BATCH 64
#define FRAMES 128
#define N_IN 512
#define N_HID 2048
#define ALPHA 0.5f
#define DECAY 0.5f
#define THR 0.5f

#define MEMS_ELEMS ((size_t)2 * BATCH * (FRAMES + 1) * N_HID)

// ---------------------------------------------------------------------------
// Device scratch
// ---------------------------------------------------------------------------
__device__ float g_U[2][BATCH * FRAMES][N_HID];  // x@W + bias
// A limbs (fp16, scaled 1 / 2^12 / 2^24), PRE-PADDED rows of 80B (conflict-free):
// [layer][ntile(64)][subchunk(16)][limb(3)][kin(128)][40 halves]  (~63MB)
__device__ __align__(256) __half g_ApackP[(size_t)2 * 64 * 16 * 3 * 128 * 40];
// x limbs (fp16 scaled)
__device__ __half g_X[3][(size_t)BATCH * FRAMES * N_IN];
// W limbs (fp16 scaled)
__device__ __half g_W[3][(size_t)2 * N_IN * N_HID];
// fp16 spike scratch, ping-pong by parity
__device__ __half g_sbf[2][2][BATCH][N_HID];
// fp32 membrane scratch, ping-pong by parity
__device__ float g_mem[2][2][BATCH][N_HID];

// 3-limb scaled fp16 split: a = h0 + h1*2^-12 + h2*2^-24 + r, |r| ~ 2^-36|a|
__device__ __forceinline__ void split3h(float a, __half& h0, __half& h1, __half& h2)
{
    float r = a;
    h0 = __float2half_rn(r);
    r -= __half2float(h0);
    h1 = __float2half_rn(r * 4096.0f);
    r -= __half2float(h1) * (1.0f / 4096.0f);
    h2 = __float2half_rn(r * 16777216.0f);
}

__global__ void prep_A3_kernel(const float* __restrict__ A1,
                               const float* __restrict__ A2)
{
    size_t per = (size_t)N_HID * N_HID;
    size_t idx = (size_t)blockIdx.x * blockDim.x + threadIdx.x;
    if (idx >= 2 * per) return;
    int layer = (int)(idx / per);
    size_t rem = idx % per;
    int k = (int)(rem / N_HID);
    int n = (int)(rem % N_HID);
    float a = (layer ? A2 : A1)[rem];

    int nt = n >> 5, col = n & 31;
    int chunk = k >> 7, kin = k & 127;
    size_t row0 = (((size_t)(layer * 64 + nt) * 16 + chunk) * 3) * 128 + kin;

    __half h0, h1, h2;
    split3h(a, h0, h1, h2);
    g_ApackP[(row0 + 0 * 128) * 40 + col] = h0;
    g_ApackP[(row0 + 1 * 128) * 40 + col] = h1;
    g_ApackP[(row0 + 2 * 128) * 40 + col] = h2;
}

__global__ void prep_x3_kernel(const float* __restrict__ x)
{
    size_t total = (size_t)BATCH * FRAMES * N_IN;
    size_t idx = (size_t)blockIdx.x * blockDim.x + threadIdx.x;
    if (idx >= total) return;
    __half h0, h1, h2;
    split3h(x[idx], h0, h1, h2);
    g_X[0][idx] = h0; g_X[1][idx] = h1; g_X[2][idx] = h2;
}

__global__ void prep_W3_kernel(const float* __restrict__ W1,
                               const float* __restrict__ W2)
{
    size_t per = (size_t)N_IN * N_HID;
    size_t idx = (size_t)blockIdx.x * blockDim.x + threadIdx.x;
    if (idx >= 2 * per) return;
    float a = (idx < per) ? W1[idx] : W2[idx - per];
    __half h0, h1, h2;
    split3h(a, h0, h1, h2);
    g_W[0][idx] = h0; g_W[1][idx] = h1; g_W[2][idx] = h2;
}

// ---------------------------------------------------------------------------
// Feedforward GEMM via fp16 wmma, 6 limb-product passes (unchanged, proven)
// ---------------------------------------------------------------------------
__global__ void __launch_bounds__(256) ff_wmma_kernel(
    const float* __restrict__ b1, const float* __restrict__ b2)
{
    const int n0 = blockIdx.x * 64;
    const int m0 = blockIdx.y * 128;
    const int layer = blockIdx.z;

    __shared__ __half Xs[128][40];
    __shared__ __half Ws[32][72];

    const int tid = threadIdx.x;
    const int wid = tid >> 5;
    const int wm = wid >> 1;
    const int wn = (wid & 1) * 2;

    wmma::fragment<wmma::accumulator, 16, 16, 16, float> ctot[2][2];
#pragma unroll
    for (int i = 0; i < 2; i++)
#pragma unroll
        for (int j = 0; j < 2; j++) wmma::fill_fragment(ctot[i][j], 0.0f);

    const int PI[6] = {0, 0, 1, 0, 2, 1};
    const int PJ[6] = {0, 1, 0, 2, 0, 1};
    const float PS[6] = {1.0f, 0x1p-12f, 0x1p-12f, 0x1p-24f, 0x1p-24f, 0x1p-24f};

#pragma unroll 1
    for (int p = 0; p < 6; p++) {
        const __half* __restrict__ Xsrc = &g_X[PI[p]][0];
        const __half* __restrict__ Wsrc = &g_W[PJ[p]][(size_t)layer * N_IN * N_HID];

        wmma::fragment<wmma::accumulator, 16, 16, 16, float> acc[2][2];
#pragma unroll
        for (int i = 0; i < 2; i++)
#pragma unroll
            for (int j = 0; j < 2; j++) wmma::fill_fragment(acc[i][j], 0.0f);

#pragma unroll 1
        for (int k0 = 0; k0 < N_IN; k0 += 32) {
#pragma unroll
            for (int i = 0; i < 2; i++) {
                int idx = tid + i * 256;
                int row = idx >> 2;
                int q = (idx & 3) * 8;
                *(uint4*)&Xs[row][q] =
                    *(const uint4*)&Xsrc[(size_t)(m0 + row) * N_IN + k0 + q];
            }
            {
                int row = tid >> 3;
                int cc = (tid & 7) * 8;
                *(uint4*)&Ws[row][cc] =
                    *(const uint4*)&Wsrc[(size_t)(k0 + row) * N_HID + n0 + cc];
            }
            __syncthreads();

#pragma unroll
            for (int ks = 0; ks < 2; ks++) {
                wmma::fragment<wmma::matrix_a, 16, 16, 16, __half, wmma::row_major> af[2];
                wmma::fragment<wmma::matrix_b, 16, 16, 16, __half, wmma::row_major> bf[2];
#pragma unroll
                for (int i = 0; i < 2; i++)
                    wmma::load_matrix_sync(af[i], &Xs[(2 * wm + i) * 16][ks * 16], 40);
#pragma unroll
                for (int j = 0; j < 2; j++)
                    wmma::load_matrix_sync(bf[j], &Ws[ks * 16][(wn + j) * 16], 72);
#pragma unroll
                for (int i = 0; i < 2; i++)
#pragma unroll
                    for (int j = 0; j < 2; j++)
                        wmma::mma_sync(acc[i][j], af[i], bf[j], acc[i][j]);
            }
            __syncthreads();
        }

        const float sc = PS[p];
#pragma unroll
        for (int i = 0; i < 2; i++)
#pragma unroll
            for (int j = 0; j < 2; j++)
#pragma unroll
                for (int e = 0; e < ctot[0][0].num_elements; e++)
                    ctot[i][j].x[e] += acc[i][j].x[e] * sc;
    }

    const float* __restrict__ bias = layer ? b2 : b1;
    __shared__ float Cs[128][72];
#pragma unroll
    for (int i = 0; i < 2; i++)
#pragma unroll
        for (int j = 0; j < 2; j++)
            wmma::store_matrix_sync(&Cs[(2 * wm + i) * 16][(wn + j) * 16],
                                    ctot[i][j], 72, wmma::mem_row_major);
    __syncthreads();
    float* __restrict__ U = &g_U[layer][0][0];
#pragma unroll
    for (int e = 0; e < 32; e++) {
        int flat = tid + e * 256;
        int row = flat >> 6;
        int col = flat & 63;
        U[(size_t)(m0 + row) * N_HID + n0 + col] = Cs[row][col] + bias[n0 + col];
    }
}

// ---------------------------------------------------------------------------
// Init t=0 state (outputs + both scratches, parity 0)
// ---------------------------------------------------------------------------
__global__ void init_kernel(const float* __restrict__ mem0_1,
                            const float* __restrict__ mem0_2,
                            float* __restrict__ out)
{
    float* mems = out;
    float* spikes = out + MEMS_ELEMS;
    size_t idx = (size_t)blockIdx.x * blockDim.x + threadIdx.x;
    size_t total = (size_t)2 * BATCH * N_HID;
    if (idx >= total) return;
    int l = (int)(idx / ((size_t)BATCH * N_HID));
    size_t rem = idx % ((size_t)BATCH * N_HID);
    int b = (int)(rem / N_HID);
    int h = (int)(rem % N_HID);
    const float* m0 = l ? mem0_2 : mem0_1;
    float mv = m0[(size_t)b * N_HID + h];
    size_t o = ((size_t)(l * BATCH + b) * (FRAMES + 1)) * N_HID + h;
    __stwt(&mems[o], mv);
    __stwt(&spikes[o], 0.f);
    g_mem[0][l][b][h] = mv;
    g_sbf[0][l][b][h] = __float2half(0.f);
}

// ---------------------------------------------------------------------------
// Fused pipelined step. Grid 128 = 2 layers x 64 coltiles(32). Block 768
// (24 warps): warp = (limb(3), m-tile(4), n-tile(2)). KC=256 (8 chunks),
// NSTAGE=2, prefetch-1. A via one TMA bulk (61440B) per stage; padded 80B
// rows (conflict-free). Halves the per-chunk protocol count vs KC=128.
// ---------------------------------------------------------------------------
#define KC 256
#define NCH (N_HID / KC)                   // 8 chunks
#define NSTAGE 2
#define SS_STAGE_BYTES (64 * 528)          // 64 rows x 264 halves = 33792
#define AS_STAGE_BYTES (2 * 3 * 128 * 80)  // 2 subchunks x 3 limbs x 128 x 80B = 61440
#define SS_OFF 0
#define AS_OFF (NSTAGE * SS_STAGE_BYTES)                  // 67584
#define CS_OFF (AS_OFF + NSTAGE * AS_STAGE_BYTES)         // 190464
#define CS_TILE_BYTES (64 * 36 * 4)                       // 9216
#define MBAR_OFF (CS_OFF + 3 * CS_TILE_BYTES)             // 218112
#define STEP_SMEM_BYTES (MBAR_OFF + NSTAGE * 8 + 48)      // 218176

__device__ __forceinline__ void cpasync16(unsigned int dst, const void* src)
{
    asm volatile("cp.async.cg.shared.global [%0], [%1], 16;\n" ::"r"(dst), "l"(src));
}
__device__ __forceinline__ void mbar_init(unsigned int mbar, unsigned int count)
{
    asm volatile("mbarrier.init.shared.b64 [%0], %1;\n" ::"r"(mbar), "r"(count) : "memory");
}
__device__ __forceinline__ void mbar_expect_tx(unsigned int mbar, unsigned int bytes)
{
    asm volatile("mbarrier.arrive.expect_tx.shared.b64 _, [%0], %1;\n"
                 ::"r"(mbar), "r"(bytes) : "memory");
}
__device__ __forceinline__ void tma_bulk_1d(unsigned int dst, const void* src,
                                            unsigned int bytes, unsigned int mbar)
{
    asm volatile(
        "cp.async.bulk.shared::cta.global.mbarrier::complete_tx::bytes "
        "[%0], [%1], %2, [%3];\n"
        ::"r"(dst), "l"(src), "r"(bytes), "r"(mbar) : "memory");
}
__device__ __forceinline__ void mbar_wait(unsigned int mbar, unsigned int parity)
{
    unsigned int done;
    asm volatile(
        "{\n\t"
        ".reg .pred p;\n\t"
        "mbarrier.try_wait.parity.acquire.cta.shared::cta.b64 p, [%1], %2;\n\t"
        "selp.b32 %0, 1, 0, p;\n\t"
        "}"
        : "=r"(done) : "r"(mbar), "r"(parity) : "memory");
    if (!done) {
        asm volatile(
            "{\n\t"
            ".reg .pred P1;\n\t"
            "WAIT_LOOP_%=:\n\t"
            "mbarrier.try_wait.parity.acquire.cta.shared::cta.b64 P1, [%0], %1, 0x989680;\n\t"
            "@P1 bra.uni WAIT_DONE_%=;\n\t"
            "bra.uni WAIT_LOOP_%=;\n\t"
            "WAIT_DONE_%=:\n\t"
            "}"
            ::"r"(mbar), "r"(parity) : "memory");
    }
}

extern __shared__ char smem_buf[];

__global__ void __launch_bounds__(768) step_mma_kernel(float* __restrict__ out, int t)
{
    const int bx = blockIdx.x;
    const int layer = bx >> 6;
    const int nt = bx & 63;
    const int n0 = nt * 32;

    const int tid = threadIdx.x;
    const int wid = tid >> 5;
    const int l   = wid >> 3;      // limb 0..2
    const int w8  = wid & 7;
    const int wm  = w8 >> 1;       // 0..3 m-tile
    const int wn  = w8 & 1;        // 0..1 n-tile

    float* mems = out;
    float* spikes = out + MEMS_ELEMS;

    // per-(layer,ntile) padded A pack: 8 chunks x 61440B, contiguous
    const __half* __restrict__ Abase =
        g_ApackP + (size_t)(layer * 64 + nt) * (16 * 3 * 128 * 40);
    const __half* __restrict__ gS = &g_sbf[t & 1][layer][0][0];
    const float* __restrict__ gM = &g_mem[t & 1][layer][0][0];

    const unsigned int smem_u32 = (unsigned int)__cvta_generic_to_shared(smem_buf);
    const unsigned int mbar0 = smem_u32 + MBAR_OFF;

    if (tid == 0) {
#pragma unroll
        for (int s = 0; s < NSTAGE; s++) mbar_init(mbar0 + s * 8, 1);
    }
    __syncthreads();

    wmma::fragment<wmma::accumulator, 16, 16, 16, float> acc;
    wmma::fill_fragment(acc, 0.0f);

    // spike copy map: first 512 threads; 64 rows x 512B, dst pitch 528B
    const int sb = (tid & 511) >> 3;
    const int scb = tid & 7;

    auto issue_stage = [&](int c, int s) {
        if (tid == 0) {
            unsigned int mb = mbar0 + s * 8;
            mbar_expect_tx(mb, AS_STAGE_BYTES);
            tma_bulk_1d(smem_u32 + AS_OFF + s * AS_STAGE_BYTES,
                        (const char*)Abase + (size_t)c * AS_STAGE_BYTES,
                        AS_STAGE_BYTES, mb);
        }
        if (tid < 512) {
            const char* srcS = (const char*)gS + (size_t)sb * (N_HID * 2) + c * (KC * 2);
            unsigned int dstS = smem_u32 + SS_OFF + s * SS_STAGE_BYTES + sb * 528;
#pragma unroll
            for (int i = 0; i < 4; i++) {
                int cc = scb + i * 8;     // 32 x 16B chunks per row
                cpasync16(dstS + cc * 16, srcS + cc * 16);
            }
        }
        asm volatile("cp.async.commit_group;\n" ::: "memory");
    };

    issue_stage(0, 0);

#pragma unroll 1
    for (int c = 0; c < NCH; c++) {
        asm volatile("cp.async.wait_group 0;\n" ::: "memory");
        const int s = c & 1;
        mbar_wait(mbar0 + s * 8, (c >> 1) & 1);
        __syncthreads();

        if (c + 1 < NCH) issue_stage(c + 1, (c + 1) & 1);

        const __half* ssb = (const __half*)(smem_buf + SS_OFF + s * SS_STAGE_BYTES);
        const __half* asb = (const __half*)(smem_buf + AS_OFF + s * AS_STAGE_BYTES);

#pragma unroll
        for (int ks = 0; ks < KC / 16; ks++) {
            const int h  = ks >> 3;      // sub-chunk 0/1
            const int kk = ks & 7;       // k-16 group within sub-chunk
            wmma::fragment<wmma::matrix_a, 16, 16, 16, __half, wmma::row_major> af;
            wmma::load_matrix_sync(af, ssb + (wm * 16) * 264 + ks * 16, 264);
            wmma::fragment<wmma::matrix_b, 16, 16, 16, __half, wmma::row_major> bfr;
            wmma::load_matrix_sync(
                bfr, asb + ((h * 3 + l) * 128 + kk * 16) * 40 + wn * 16, 40);
            wmma::mma_sync(acc, af, bfr, acc);
        }
    }

    // store raw per-limb partials; scaling happens in the epilogue
    float* Cl = (float*)(smem_buf + CS_OFF + l * CS_TILE_BYTES);
    __syncthreads();
    wmma::store_matrix_sync(Cl + (wm * 16) * 36 + wn * 16, acc, 36,
                            wmma::mem_row_major);
    __syncthreads();

    // fused LIF epilogue: p = fma(c1, 2^-12, c0) + c2*2^-24
    const float* Cs0 = (const float*)(smem_buf + CS_OFF);
    const float* Cs1 = (const float*)(smem_buf + CS_OFF + CS_TILE_BYTES);
    const float* Cs2 = (const float*)(smem_buf + CS_OFF + 2 * CS_TILE_BYTES);
    __half* gSn = &g_sbf[(t + 1) & 1][layer][0][0];
    float* gMn = &g_mem[(t + 1) & 1][layer][0][0];
#pragma unroll
    for (int e = 0; e < 3; e++) {
        int flat = tid + e * 768;   // 0..2303, guard to 2048
        if (flat < 2048) {
            int b = flat >> 5;
            int hl = flat & 31;
            int h = n0 + hl;
            float p = fmaf(Cs1[b * 36 + hl], 0x1p-12f, Cs0[b * 36 + hl])
                      + Cs2[b * 36 + hl] * 0x1p-24f;
            float u = __ldcs(&g_U[layer][b * FRAMES + t][h]);
            size_t row_t1 =
                ((size_t)(layer * BATCH + b) * (FRAMES + 1) + t + 1) * N_HID + h;
            float mprev = gM[(size_t)b * N_HID + h];
            float sprev = __half2float(gS[(size_t)b * N_HID + h]);
            float y = tanhf(ALPHA * p + (1.0f - ALPHA) * u);
            float mn = DECAY * mprev - THR * (1.0f - sprev) + y;
            float sn = (mn > THR) ? 1.0f : 0.0f;
            __stwt(&mems[row_t1], mn);
            __stwt(&spikes[row_t1], sn);
            gMn[(size_t)b * N_HID + h] = mn;
            gSn[(size_t)b * N_HID + h] = __float2half(sn);
        }
    }
}

// ---------------------------------------------------------------------------
// Launch. Inputs: x, W_in1, A1, b1, W_in2, A2, b2, mem0_1, mem0_2
// ---------------------------------------------------------------------------
extern "C" void kernel_launch(void* const* d_in, const int* in_sizes, int n_in,
                              void* d_out, int out_size)
{
    const float* x      = (const float*)d_in[0];
    const float* W_in1  = (const float*)d_in[1];
    const float* A1     = (const float*)d_in[2];
    const float* b1     = (const float*)d_in[3];
    const float* W_in2  = (const float*)d_in[4];
    const float* A2     = (const float*)d_in[5];
    const float* b2     = (const float*)d_in[6];
    const float* mem0_1 = (const float*)d_in[7];
    const float* mem0_2 = (const float*)d_in[8];
    float* out = (float*)d_out;

    cudaFuncSetAttribute(step_mma_kernel,
                         cudaFuncAttributeMaxDynamicSharedMemorySize,
                         STEP_SMEM_BYTES);

    // limb packs
    {
        size_t n = (size_t)2 * N_HID * N_HID;
        prep_A3_kernel<<<(unsigned)((n + 255) / 256), 256>>>(A1, A2);
    }
    {
        size_t n = (size_t)BATCH * FRAMES * N_IN;
        prep_x3_kernel<<<(unsigned)((n + 255) / 256), 256>>>(x);
    }
    {
        size_t n = (size_t)2 * N_IN * N_HID;
        prep_W3_kernel<<<(unsigned)((n + 255) / 256), 256>>>(W_in1, W_in2);
    }

    // Feedforward drive on tensor cores (includes bias)
    {
        dim3 grid(N_HID / 64, (BATCH * FRAMES) / 128, 2);
        ff_wmma_kernel<<<grid, 256>>>(b1, b2);
    }

    // t=0 state
    {
        int total = 2 * BATCH * N_HID;
        init_kernel<<<(total + 255) / 256, 256>>>(mem0_1, mem0_2, out);
    }

    // Sequential time loop
    for (int t = 0; t < FRAMES; t++) {
        step_mma_kernel<<<128, 768, STEP_SMEM_BYTES>>>(out, t);
    }
}

// round 17
// speedup vs baseline: 3.2393x; 1.1196x over previous
#include <cuda_runtime.h>
#include <cuda_bf16.h>
#include <cuda_fp16.h>
#include <mma.h>
#include <math.h>
#include <cstdint>
#include <cstddef>

using namespace nvcuda;

#define BATCH 64
#define FRAMES 128
#define N_IN 512
#define N_HID 2048
#define ALPHA 0.5f
#define DECAY 0.5f
#define THR 0.5f

#define MEMS_ELEMS ((size_t)2 * BATCH * (FRAMES + 1) * N_HID)

// ---------------------------------------------------------------------------
// Device scratch
// ---------------------------------------------------------------------------
__device__ float g_U[2][BATCH * FRAMES][N_HID];  // x@W + bias
// A limbs (fp16, scaled 1 / 2^12 / 2^24), PRE-PADDED rows of 80B (conflict-free):
// [layer][ntile(64)][subchunk(16)][limb(3)][kin(128)][40 halves]  (~63MB)
__device__ __align__(256) __half g_ApackP[(size_t)2 * 64 * 16 * 3 * 128 * 40];
// x limbs (fp16 scaled)
__device__ __half g_X[3][(size_t)BATCH * FRAMES * N_IN];
// W limbs (fp16 scaled)
__device__ __half g_W[3][(size_t)2 * N_IN * N_HID];
// fp16 spike scratch, ping-pong by parity
__device__ __half g_sbf[2][2][BATCH][N_HID];
// fp32 membrane scratch, ping-pong by parity
__device__ float g_mem[2][2][BATCH][N_HID];

// 3-limb scaled fp16 split: a = h0 + h1*2^-12 + h2*2^-24 + r, |r| ~ 2^-36|a|
__device__ __forceinline__ void split3h(float a, __half& h0, __half& h1, __half& h2)
{
    float r = a;
    h0 = __float2half_rn(r);
    r -= __half2float(h0);
    h1 = __float2half_rn(r * 4096.0f);
    r -= __half2float(h1) * (1.0f / 4096.0f);
    h2 = __float2half_rn(r * 16777216.0f);
}

__global__ void prep_A3_kernel(const float* __restrict__ A1,
                               const float* __restrict__ A2)
{
    size_t per = (size_t)N_HID * N_HID;
    size_t idx = (size_t)blockIdx.x * blockDim.x + threadIdx.x;
    if (idx >= 2 * per) return;
    int layer = (int)(idx / per);
    size_t rem = idx % per;
    int k = (int)(rem / N_HID);
    int n = (int)(rem % N_HID);
    float a = (layer ? A2 : A1)[rem];

    int nt = n >> 5, col = n & 31;
    int chunk = k >> 7, kin = k & 127;
    size_t row0 = (((size_t)(layer * 64 + nt) * 16 + chunk) * 3) * 128 + kin;

    __half h0, h1, h2;
    split3h(a, h0, h1, h2);
    g_ApackP[(row0 + 0 * 128) * 40 + col] = h0;
    g_ApackP[(row0 + 1 * 128) * 40 + col] = h1;
    g_ApackP[(row0 + 2 * 128) * 40 + col] = h2;
}

__global__ void prep_x3_kernel(const float* __restrict__ x)
{
    size_t total = (size_t)BATCH * FRAMES * N_IN;
    size_t idx = (size_t)blockIdx.x * blockDim.x + threadIdx.x;
    if (idx >= total) return;
    __half h0, h1, h2;
    split3h(x[idx], h0, h1, h2);
    g_X[0][idx] = h0; g_X[1][idx] = h1; g_X[2][idx] = h2;
}

__global__ void prep_W3_kernel(const float* __restrict__ W1,
                               const float* __restrict__ W2)
{
    size_t per = (size_t)N_IN * N_HID;
    size_t idx = (size_t)blockIdx.x * blockDim.x + threadIdx.x;
    if (idx >= 2 * per) return;
    float a = (idx < per) ? W1[idx] : W2[idx - per];
    __half h0, h1, h2;
    split3h(a, h0, h1, h2);
    g_W[0][idx] = h0; g_W[1][idx] = h1; g_W[2][idx] = h2;
}

// ---------------------------------------------------------------------------
// Feedforward GEMM via fp16 wmma, 6 limb-product passes (unchanged, proven)
// ---------------------------------------------------------------------------
__global__ void __launch_bounds__(256) ff_wmma_kernel(
    const float* __restrict__ b1, const float* __restrict__ b2)
{
    const int n0 = blockIdx.x * 64;
    const int m0 = blockIdx.y * 128;
    const int layer = blockIdx.z;

    __shared__ __half Xs[128][40];
    __shared__ __half Ws[32][72];

    const int tid = threadIdx.x;
    const int wid = tid >> 5;
    const int wm = wid >> 1;
    const int wn = (wid & 1) * 2;

    wmma::fragment<wmma::accumulator, 16, 16, 16, float> ctot[2][2];
#pragma unroll
    for (int i = 0; i < 2; i++)
#pragma unroll
        for (int j = 0; j < 2; j++) wmma::fill_fragment(ctot[i][j], 0.0f);

    const int PI[6] = {0, 0, 1, 0, 2, 1};
    const int PJ[6] = {0, 1, 0, 2, 0, 1};
    const float PS[6] = {1.0f, 0x1p-12f, 0x1p-12f, 0x1p-24f, 0x1p-24f, 0x1p-24f};

#pragma unroll 1
    for (int p = 0; p < 6; p++) {
        const __half* __restrict__ Xsrc = &g_X[PI[p]][0];
        const __half* __restrict__ Wsrc = &g_W[PJ[p]][(size_t)layer * N_IN * N_HID];

        wmma::fragment<wmma::accumulator, 16, 16, 16, float> acc[2][2];
#pragma unroll
        for (int i = 0; i < 2; i++)
#pragma unroll
            for (int j = 0; j < 2; j++) wmma::fill_fragment(acc[i][j], 0.0f);

#pragma unroll 1
        for (int k0 = 0; k0 < N_IN; k0 += 32) {
#pragma unroll
            for (int i = 0; i < 2; i++) {
                int idx = tid + i * 256;
                int row = idx >> 2;
                int q = (idx & 3) * 8;
                *(uint4*)&Xs[row][q] =
                    *(const uint4*)&Xsrc[(size_t)(m0 + row) * N_IN + k0 + q];
            }
            {
                int row = tid >> 3;
                int cc = (tid & 7) * 8;
                *(uint4*)&Ws[row][cc] =
                    *(const uint4*)&Wsrc[(size_t)(k0 + row) * N_HID + n0 + cc];
            }
            __syncthreads();

#pragma unroll
            for (int ks = 0; ks < 2; ks++) {
                wmma::fragment<wmma::matrix_a, 16, 16, 16, __half, wmma::row_major> af[2];
                wmma::fragment<wmma::matrix_b, 16, 16, 16, __half, wmma::row_major> bf[2];
#pragma unroll
                for (int i = 0; i < 2; i++)
                    wmma::load_matrix_sync(af[i], &Xs[(2 * wm + i) * 16][ks * 16], 40);
#pragma unroll
                for (int j = 0; j < 2; j++)
                    wmma::load_matrix_sync(bf[j], &Ws[ks * 16][(wn + j) * 16], 72);
#pragma unroll
                for (int i = 0; i < 2; i++)
#pragma unroll
                    for (int j = 0; j < 2; j++)
                        wmma::mma_sync(acc[i][j], af[i], bf[j], acc[i][j]);
            }
            __syncthreads();
        }

        const float sc = PS[p];
#pragma unroll
        for (int i = 0; i < 2; i++)
#pragma unroll
            for (int j = 0; j < 2; j++)
#pragma unroll
                for (int e = 0; e < ctot[0][0].num_elements; e++)
                    ctot[i][j].x[e] += acc[i][j].x[e] * sc;
    }

    const float* __restrict__ bias = layer ? b2 : b1;
    __shared__ float Cs[128][72];
#pragma unroll
    for (int i = 0; i < 2; i++)
#pragma unroll
        for (int j = 0; j < 2; j++)
            wmma::store_matrix_sync(&Cs[(2 * wm + i) * 16][(wn + j) * 16],
                                    ctot[i][j], 72, wmma::mem_row_major);
    __syncthreads();
    float* __restrict__ U = &g_U[layer][0][0];
#pragma unroll
    for (int e = 0; e < 32; e++) {
        int flat = tid + e * 256;
        int row = flat >> 6;
        int col = flat & 63;
        U[(size_t)(m0 + row) * N_HID + n0 + col] = Cs[row][col] + bias[n0 + col];
    }
}

// ---------------------------------------------------------------------------
// Init t=0 state (outputs + both scratches, parity 0)
// ---------------------------------------------------------------------------
__global__ void init_kernel(const float* __restrict__ mem0_1,
                            const float* __restrict__ mem0_2,
                            float* __restrict__ out)
{
    float* mems = out;
    float* spikes = out + MEMS_ELEMS;
    size_t idx = (size_t)blockIdx.x * blockDim.x + threadIdx.x;
    size_t total = (size_t)2 * BATCH * N_HID;
    if (idx >= total) return;
    int l = (int)(idx / ((size_t)BATCH * N_HID));
    size_t rem = idx % ((size_t)BATCH * N_HID);
    int b = (int)(rem / N_HID);
    int h = (int)(rem % N_HID);
    const float* m0 = l ? mem0_2 : mem0_1;
    float mv = m0[(size_t)b * N_HID + h];
    size_t o = ((size_t)(l * BATCH + b) * (FRAMES + 1)) * N_HID + h;
    __stwt(&mems[o], mv);
    __stwt(&spikes[o], 0.f);
    g_mem[0][l][b][h] = mv;
    g_sbf[0][l][b][h] = __float2half(0.f);
}

// ---------------------------------------------------------------------------
// Fused pipelined step. Grid 128 = 2 layers x 64 coltiles(32). Block 512
// (16 warps): warp = (kh(4) x m-half(2) x n-half(2)); each warp owns all 3
// limbs + 2 m-fragments -> 58% less smem fragment traffic than R15 mapping.
// KC=256 (8 chunks), NSTAGE=2, prefetch-1, TMA bulk for A.
// k-split partials reduced in the epilogue (pairwise), then limb combine.
// ---------------------------------------------------------------------------
#define KC 256
#define NCH (N_HID / KC)                   // 8 chunks
#define NSTAGE 2
#define SS_STAGE_BYTES (64 * 528)          // 64 rows x 264 halves = 33792
#define AS_STAGE_BYTES (2 * 3 * 128 * 80)  // 61440
#define SS_OFF 0
#define AS_OFF (NSTAGE * SS_STAGE_BYTES)                  // 67584
#define CS_TILE_BYTES (64 * 36 * 4)                       // 9216
// partials live in the stage region after the main loop (12 x 9216 = 110592)
#define MBAR_OFF (AS_OFF + NSTAGE * AS_STAGE_BYTES)       // 190464
#define STEP_SMEM_BYTES (MBAR_OFF + NSTAGE * 8 + 48)      // 190528

__device__ __forceinline__ void cpasync16(unsigned int dst, const void* src)
{
    asm volatile("cp.async.cg.shared.global [%0], [%1], 16;\n" ::"r"(dst), "l"(src));
}
__device__ __forceinline__ void mbar_init(unsigned int mbar, unsigned int count)
{
    asm volatile("mbarrier.init.shared.b64 [%0], %1;\n" ::"r"(mbar), "r"(count) : "memory");
}
__device__ __forceinline__ void mbar_expect_tx(unsigned int mbar, unsigned int bytes)
{
    asm volatile("mbarrier.arrive.expect_tx.shared.b64 _, [%0], %1;\n"
                 ::"r"(mbar), "r"(bytes) : "memory");
}
__device__ __forceinline__ void tma_bulk_1d(unsigned int dst, const void* src,
                                            unsigned int bytes, unsigned int mbar)
{
    asm volatile(
        "cp.async.bulk.shared::cta.global.mbarrier::complete_tx::bytes "
        "[%0], [%1], %2, [%3];\n"
        ::"r"(dst), "l"(src), "r"(bytes), "r"(mbar) : "memory");
}
__device__ __forceinline__ void mbar_wait(unsigned int mbar, unsigned int parity)
{
    unsigned int done;
    asm volatile(
        "{\n\t"
        ".reg .pred p;\n\t"
        "mbarrier.try_wait.parity.acquire.cta.shared::cta.b64 p, [%1], %2;\n\t"
        "selp.b32 %0, 1, 0, p;\n\t"
        "}"
        : "=r"(done) : "r"(mbar), "r"(parity) : "memory");
    if (!done) {
        asm volatile(
            "{\n\t"
            ".reg .pred P1;\n\t"
            "WAIT_LOOP_%=:\n\t"
            "mbarrier.try_wait.parity.acquire.cta.shared::cta.b64 P1, [%0], %1, 0x989680;\n\t"
            "@P1 bra.uni WAIT_DONE_%=;\n\t"
            "bra.uni WAIT_LOOP_%=;\n\t"
            "WAIT_DONE_%=:\n\t"
            "}"
            ::"r"(mbar), "r"(parity) : "memory");
    }
}

extern __shared__ char smem_buf[];

__global__ void __launch_bounds__(512) step_mma_kernel(float* __restrict__ out, int t)
{
    const int bx = blockIdx.x;
    const int layer = bx >> 6;
    const int nt = bx & 63;
    const int n0 = nt * 32;

    const int tid = threadIdx.x;
    const int wid = tid >> 5;
    const int kh = wid >> 2;       // 0..3 k-split: ks in [kh*4, kh*4+4)
    const int wm = (wid >> 1) & 1; // m-half: rows wm*32 .. wm*32+31
    const int wn = wid & 1;        // n-half: cols wn*16 .. wn*16+15

    float* mems = out;
    float* spikes = out + MEMS_ELEMS;

    const __half* __restrict__ Abase =
        g_ApackP + (size_t)(layer * 64 + nt) * (16 * 3 * 128 * 40);
    const __half* __restrict__ gS = &g_sbf[t & 1][layer][0][0];
    const float* __restrict__ gM = &g_mem[t & 1][layer][0][0];

    const unsigned int smem_u32 = (unsigned int)__cvta_generic_to_shared(smem_buf);
    const unsigned int mbar0 = smem_u32 + MBAR_OFF;

    if (tid == 0) {
#pragma unroll
        for (int s = 0; s < NSTAGE; s++) mbar_init(mbar0 + s * 8, 1);
    }
    __syncthreads();

    // 6 accumulators: [m-frag 2][limb 3]
    wmma::fragment<wmma::accumulator, 16, 16, 16, float> acc[2][3];
#pragma unroll
    for (int i = 0; i < 2; i++)
#pragma unroll
        for (int l = 0; l < 3; l++) wmma::fill_fragment(acc[i][l], 0.0f);

    // spike copy map: all 512 threads; 64 rows x 512B, dst pitch 528B
    const int sb = tid >> 3;
    const int scb = tid & 7;

    auto issue_stage = [&](int c, int s) {
        if (tid == 0) {
            unsigned int mb = mbar0 + s * 8;
            mbar_expect_tx(mb, AS_STAGE_BYTES);
            tma_bulk_1d(smem_u32 + AS_OFF + s * AS_STAGE_BYTES,
                        (const char*)Abase + (size_t)c * AS_STAGE_BYTES,
                        AS_STAGE_BYTES, mb);
        }
        {
            const char* srcS = (const char*)gS + (size_t)sb * (N_HID * 2) + c * (KC * 2);
            unsigned int dstS = smem_u32 + SS_OFF + s * SS_STAGE_BYTES + sb * 528;
#pragma unroll
            for (int i = 0; i < 4; i++) {
                int cc = scb + i * 8;
                cpasync16(dstS + cc * 16, srcS + cc * 16);
            }
        }
        asm volatile("cp.async.commit_group;\n" ::: "memory");
    };

    issue_stage(0, 0);

#pragma unroll 1
    for (int c = 0; c < NCH; c++) {
        asm volatile("cp.async.wait_group 0;\n" ::: "memory");
        const int s = c & 1;
        mbar_wait(mbar0 + s * 8, (c >> 1) & 1);
        __syncthreads();

        if (c + 1 < NCH) issue_stage(c + 1, (c + 1) & 1);

        const __half* ssb = (const __half*)(smem_buf + SS_OFF + s * SS_STAGE_BYTES);
        const __half* asb = (const __half*)(smem_buf + AS_OFF + s * AS_STAGE_BYTES);

#pragma unroll
        for (int ksl = 0; ksl < 4; ksl++) {
            const int ks = kh * 4 + ksl;
            const int h  = ks >> 3;      // sub-chunk 0/1
            const int kk = ks & 7;       // k-16 group within sub-chunk
            wmma::fragment<wmma::matrix_a, 16, 16, 16, __half, wmma::row_major> af[2];
#pragma unroll
            for (int i = 0; i < 2; i++)
                wmma::load_matrix_sync(af[i], ssb + ((wm * 32 + i * 16)) * 264 + ks * 16, 264);
#pragma unroll
            for (int l = 0; l < 3; l++) {
                wmma::fragment<wmma::matrix_b, 16, 16, 16, __half, wmma::row_major> bfr;
                wmma::load_matrix_sync(
                    bfr, asb + ((h * 3 + l) * 128 + kk * 16) * 40 + wn * 16, 40);
#pragma unroll
                for (int i = 0; i < 2; i++)
                    wmma::mma_sync(acc[i][l], af[i], bfr, acc[i][l]);
            }
        }
    }

    // store k-split partials into the (now free) stage region: tile [kh*3+l]
    __syncthreads();
#pragma unroll
    for (int l = 0; l < 3; l++) {
        float* Cl = (float*)(smem_buf + (kh * 3 + l) * CS_TILE_BYTES);
#pragma unroll
        for (int i = 0; i < 2; i++)
            wmma::store_matrix_sync(Cl + (wm * 32 + i * 16) * 36 + wn * 16,
                                    acc[i][l], 36, wmma::mem_row_major);
    }
    __syncthreads();

    // epilogue: reduce kh partials pairwise per limb, then limb combine + LIF
    __half* gSn = &g_sbf[(t + 1) & 1][layer][0][0];
    float* gMn = &g_mem[(t + 1) & 1][layer][0][0];
#pragma unroll
    for (int e = 0; e < 4; e++) {
        int flat = tid + e * 512;   // 0..2047
        int b = flat >> 5;
        int hl = flat & 31;
        int h = n0 + hl;
        int o = b * 36 + hl;
        float cl[3];
#pragma unroll
        for (int l = 0; l < 3; l++) {
            float p0 = ((const float*)(smem_buf + (0 * 3 + l) * CS_TILE_BYTES))[o];
            float p1 = ((const float*)(smem_buf + (1 * 3 + l) * CS_TILE_BYTES))[o];
            float p2 = ((const float*)(smem_buf + (2 * 3 + l) * CS_TILE_BYTES))[o];
            float p3 = ((const float*)(smem_buf + (3 * 3 + l) * CS_TILE_BYTES))[o];
            cl[l] = (p0 + p1) + (p2 + p3);
        }
        float p = fmaf(cl[1], 0x1p-12f, cl[0]) + cl[2] * 0x1p-24f;
        float u = __ldcs(&g_U[layer][b * FRAMES + t][h]);
        size_t row_t1 =
            ((size_t)(layer * BATCH + b) * (FRAMES + 1) + t + 1) * N_HID + h;
        float mprev = gM[(size_t)b * N_HID + h];
        float sprev = __half2float(gS[(size_t)b * N_HID + h]);
        float y = tanhf(ALPHA * p + (1.0f - ALPHA) * u);
        float mn = DECAY * mprev - THR * (1.0f - sprev) + y;
        float sn = (mn > THR) ? 1.0f : 0.0f;
        __stwt(&mems[row_t1], mn);
        __stwt(&spikes[row_t1], sn);
        gMn[(size_t)b * N_HID + h] = mn;
        gSn[(size_t)b * N_HID + h] = __float2half(sn);
    }
}

// ---------------------------------------------------------------------------
// Launch. Inputs: x, W_in1, A1, b1, W_in2, A2, b2, mem0_1, mem0_2
// ---------------------------------------------------------------------------
extern "C" void kernel_launch(void* const* d_in, const int* in_sizes, int n_in,
                              void* d_out, int out_size)
{
    const float* x      = (const float*)d_in[0];
    const float* W_in1  = (const float*)d_in[1];
    const float* A1     = (const float*)d_in[2];
    const float* b1     = (const float*)d_in[3];
    const float* W_in2  = (const float*)d_in[4];
    const float* A2     = (const float*)d_in[5];
    const float* b2     = (const float*)d_in[6];
    const float* mem0_1 = (const float*)d_in[7];
    const float* mem0_2 = (const float*)d_in[8];
    float* out = (float*)d_out;

    cudaFuncSetAttribute(step_mma_kernel,
                         cudaFuncAttributeMaxDynamicSharedMemorySize,
                         STEP_SMEM_BYTES);

    // limb packs
    {
        size_t n = (size_t)2 * N_HID * N_HID;
        prep_A3_kernel<<<(unsigned)((n + 255) / 256), 256>>>(A1, A2);
    }
    {
        size_t n = (size_t)BATCH * FRAMES * N_IN;
        prep_x3_kernel<<<(unsigned)((n + 255) / 256), 256>>>(x);
    }
    {
        size_t n = (size_t)2 * N_IN * N_HID;
        prep_W3_kernel<<<(unsigned)((n + 255) / 256), 256>>>(W_in1, W_in2);
    }

    // Feedforward drive on tensor cores (includes bias)
    {
        dim3 grid(N_HID / 64, (BATCH * FRAMES) / 128, 2);
        ff_wmma_kernel<<<grid, 256>>>(b1, b2);
    }

    // t=0 state
    {
        int total = 2 * BATCH * N_HID;
        init_kernel<<<(total + 255) / 256, 256>>>(mem0_1, mem0_2, out);
    }

    // Sequential time loop
    for (int t = 0; t < FRAMES; t++) {
        step_mma_kernel<<<128, 512, STEP_SMEM_BYTES>>>(out, t);
    }
}